// round 2
// baseline (speedup 1.0000x reference)
#include <cuda_runtime.h>

#define NN 100000
#define NE 1600000
#define NODE_IN 32
#define HID 64

// ---------------- scratch (device globals; no runtime allocation) ----------
__device__ int   g_cnt[NN];
__device__ int   g_rowptr[NN + 1];
__device__ int   g_wp[NN];
__device__ int   g_esrc[NE];
__device__ float g_mean[(size_t)NN * HID];
__device__ float g_h1[(size_t)NN * HID];
__device__ float g_h2[(size_t)NN * HID];
__device__ float g_h3[(size_t)NN * HID];
__device__ float g_u[(size_t)NN * HID];
__device__ float g_v[(size_t)NN * HID];

// ---------------- packed f32x2 helpers -------------------------------------
__device__ __forceinline__ unsigned long long ffma2(unsigned long long a,
                                                    unsigned long long b,
                                                    unsigned long long c) {
    unsigned long long d;
    asm("fma.rn.f32x2 %0, %1, %2, %3;" : "=l"(d) : "l"(a), "l"(b), "l"(c));
    return d;
}

// ---------------- CSR build -------------------------------------------------
__global__ void zero_cnt_kernel() {
    int i = blockIdx.x * blockDim.x + threadIdx.x;
    if (i < NN) g_cnt[i] = 0;
}

__global__ void hist_kernel(const int* __restrict__ dst) {
    int e = blockIdx.x * blockDim.x + threadIdx.x;
    if (e < NE) atomicAdd(&g_cnt[dst[e]], 1);
}

__global__ void scan_kernel() {
    __shared__ int wsum[32];
    __shared__ int carry;
    int tid = threadIdx.x;
    int lane = tid & 31, wid = tid >> 5;
    if (tid == 0) carry = 0;
    __syncthreads();
    for (int base = 0; base < NN; base += 1024) {
        int i = base + tid;
        int v = (i < NN) ? g_cnt[i] : 0;
        int x = v;
        #pragma unroll
        for (int o = 1; o < 32; o <<= 1) {
            int t = __shfl_up_sync(0xffffffffu, x, o);
            if (lane >= o) x += t;
        }
        if (lane == 31) wsum[wid] = x;
        __syncthreads();
        if (wid == 0) {
            int ws = wsum[lane];
            #pragma unroll
            for (int o = 1; o < 32; o <<= 1) {
                int t = __shfl_up_sync(0xffffffffu, ws, o);
                if (lane >= o) ws += t;
            }
            wsum[lane] = ws;
        }
        __syncthreads();
        int excl = carry + x - v + (wid > 0 ? wsum[wid - 1] : 0);
        if (i < NN) { g_rowptr[i] = excl; g_wp[i] = excl; }
        int total = wsum[31];
        __syncthreads();
        if (tid == 0) carry += total;
        __syncthreads();
    }
    if (tid == 0) g_rowptr[NN] = carry;
}

__global__ void fill_kernel(const int* __restrict__ src, const int* __restrict__ dst) {
    int e = blockIdx.x * blockDim.x + threadIdx.x;
    if (e < NE) {
        int pos = atomicAdd(&g_wp[dst[e]], 1);
        g_esrc[pos] = src[e];
    }
}

// ---------------- mean aggregation (warp per node, gather-only) ------------
template <int F>
__global__ void agg_kernel(const float* __restrict__ h, float* __restrict__ out) {
    int warp = (blockIdx.x * blockDim.x + threadIdx.x) >> 5;
    if (warp >= NN) return;
    int lane = threadIdx.x & 31;
    int beg = g_rowptr[warp];
    int end = g_rowptr[warp + 1];
    int deg = end - beg;
    float inv = 1.0f / (float)(deg > 0 ? deg : 1);
    if (F == 64) {
        float2 acc0 = make_float2(0.f, 0.f);
        float2 acc1 = make_float2(0.f, 0.f);
        for (int cb = beg; cb < end; cb += 32) {
            int m = min(32, end - cb);
            int sl = g_esrc[cb + ((lane < m) ? lane : 0)];
            int j = 0;
            for (; j + 2 <= m; j += 2) {
                int s0 = __shfl_sync(0xffffffffu, sl, j);
                int s1 = __shfl_sync(0xffffffffu, sl, j + 1);
                float2 v0 = __ldg(((const float2*)h) + (size_t)s0 * 32 + lane);
                float2 v1 = __ldg(((const float2*)h) + (size_t)s1 * 32 + lane);
                acc0.x += v0.x; acc0.y += v0.y;
                acc1.x += v1.x; acc1.y += v1.y;
            }
            if (j < m) {
                int s0 = __shfl_sync(0xffffffffu, sl, j);
                float2 v0 = __ldg(((const float2*)h) + (size_t)s0 * 32 + lane);
                acc0.x += v0.x; acc0.y += v0.y;
            }
        }
        float2 r = make_float2((acc0.x + acc1.x) * inv, (acc0.y + acc1.y) * inv);
        ((float2*)out)[(size_t)warp * 32 + lane] = r;
    } else {  // F == 32: one float per lane
        float acc0 = 0.f, acc1 = 0.f;
        for (int cb = beg; cb < end; cb += 32) {
            int m = min(32, end - cb);
            int sl = g_esrc[cb + ((lane < m) ? lane : 0)];
            int j = 0;
            for (; j + 2 <= m; j += 2) {
                int s0 = __shfl_sync(0xffffffffu, sl, j);
                int s1 = __shfl_sync(0xffffffffu, sl, j + 1);
                acc0 += __ldg(h + (size_t)s0 * 32 + lane);
                acc1 += __ldg(h + (size_t)s1 * 32 + lane);
            }
            if (j < m) {
                int s0 = __shfl_sync(0xffffffffu, sl, j);
                acc0 += __ldg(h + (size_t)s0 * 32 + lane);
            }
        }
        out[(size_t)warp * 32 + lane] = (acc0 + acc1) * inv;
    }
}

// ---------------- fused SAGE linear: out = [relu](mean@Wl + bl + h@Wr) -----
// warp per node; lane j computes outputs j and j+32.
template <int FIN, bool RELU>
__global__ void sage_gemm_kernel(const float* __restrict__ mean,
                                 const float* __restrict__ h,
                                 const float* __restrict__ Wl,
                                 const float* __restrict__ bl,
                                 const float* __restrict__ Wr,
                                 float* __restrict__ out) {
    __shared__ float4 sW[FIN][32];  // (Wl[k][j], Wr[k][j], Wl[k][j+32], Wr[k][j+32])
    for (int idx = threadIdx.x; idx < FIN * 32; idx += blockDim.x) {
        int k = idx >> 5, j = idx & 31;
        sW[k][j] = make_float4(Wl[k * 64 + j], Wr[k * 64 + j],
                               Wl[k * 64 + j + 32], Wr[k * 64 + j + 32]);
    }
    __syncthreads();
    int node = blockIdx.x * (blockDim.x >> 5) + (threadIdx.x >> 5);
    if (node >= NN) return;
    int lane = threadIdx.x & 31;
    const float4* mrow = (const float4*)(mean + (size_t)node * FIN);
    const float4* hrow = (const float4*)(h + (size_t)node * FIN);
    float a0 = __ldg(bl + lane);
    float a1 = __ldg(bl + lane + 32);
    #pragma unroll 4
    for (int kv = 0; kv < FIN / 4; kv++) {
        float4 m4 = __ldg(mrow + kv);
        float4 h4 = __ldg(hrow + kv);
        {
            float4 w = sW[4 * kv + 0][lane];
            a0 += m4.x * w.x + h4.x * w.y; a1 += m4.x * w.z + h4.x * w.w;
        }
        {
            float4 w = sW[4 * kv + 1][lane];
            a0 += m4.y * w.x + h4.y * w.y; a1 += m4.y * w.z + h4.y * w.w;
        }
        {
            float4 w = sW[4 * kv + 2][lane];
            a0 += m4.z * w.x + h4.z * w.y; a1 += m4.z * w.z + h4.z * w.w;
        }
        {
            float4 w = sW[4 * kv + 3][lane];
            a0 += m4.w * w.x + h4.w * w.y; a1 += m4.w * w.z + h4.w * w.w;
        }
    }
    if (RELU) { a0 = fmaxf(a0, 0.f); a1 = fmaxf(a1, 0.f); }
    out[(size_t)node * 64 + lane] = a0;
    out[(size_t)node * 64 + lane + 32] = a1;
}

// ---------------- per-node edge-MLP precompute: U = h@W1a + b1, V = h@W1b --
__global__ void uv_kernel(const float* __restrict__ W1, const float* __restrict__ b1) {
    __shared__ float4 sW[64][32];  // (W1a[k][j], W1b[k][j], W1a[k][j+32], W1b[k][j+32])
    for (int idx = threadIdx.x; idx < 64 * 32; idx += blockDim.x) {
        int k = idx >> 5, j = idx & 31;
        sW[k][j] = make_float4(W1[k * 64 + j], W1[(64 + k) * 64 + j],
                               W1[k * 64 + j + 32], W1[(64 + k) * 64 + j + 32]);
    }
    __syncthreads();
    int node = blockIdx.x * (blockDim.x >> 5) + (threadIdx.x >> 5);
    if (node >= NN) return;
    int lane = threadIdx.x & 31;
    const float4* hrow = (const float4*)(g_h3 + (size_t)node * 64);
    float u0 = __ldg(b1 + lane), u1 = __ldg(b1 + lane + 32);
    float v0 = 0.f, v1 = 0.f;
    #pragma unroll 4
    for (int kv = 0; kv < 16; kv++) {
        float4 h4 = __ldg(hrow + kv);
        {
            float4 w = sW[4 * kv + 0][lane];
            u0 += h4.x * w.x; v0 += h4.x * w.y; u1 += h4.x * w.z; v1 += h4.x * w.w;
        }
        {
            float4 w = sW[4 * kv + 1][lane];
            u0 += h4.y * w.x; v0 += h4.y * w.y; u1 += h4.y * w.z; v1 += h4.y * w.w;
        }
        {
            float4 w = sW[4 * kv + 2][lane];
            u0 += h4.z * w.x; v0 += h4.z * w.y; u1 += h4.z * w.z; v1 += h4.z * w.w;
        }
        {
            float4 w = sW[4 * kv + 3][lane];
            u0 += h4.w * w.x; v0 += h4.w * w.y; u1 += h4.w * w.z; v1 += h4.w * w.w;
        }
    }
    g_u[(size_t)node * 64 + lane] = u0;
    g_u[(size_t)node * 64 + lane + 32] = u1;
    g_v[(size_t)node * 64 + lane] = v0;
    g_v[(size_t)node * 64 + lane + 32] = v1;
}

// ---------------- edge MLP: thread per edge, f32x2-packed z2 ---------------
__global__ __launch_bounds__(256)
void edge_kernel(const int* __restrict__ esrc, const int* __restrict__ edst,
                 const float* __restrict__ eattr,
                 const float* __restrict__ W1, const float* __restrict__ W2,
                 const float* __restrict__ b2v, const float* __restrict__ W3,
                 const float* __restrict__ b3v, float* __restrict__ out) {
    __shared__ float  sW1e[64 * 8];   // [j*8 + i] = W1[(128+i)*64 + j]
    __shared__ float2 sW2[64 * 16];   // [j*16 + k] = (W2[j][2k], W2[j][2k+1])
    __shared__ float2 sb2[16];
    __shared__ float  sW3[32];
    __shared__ float  sb3;
    int tid = threadIdx.x;
    for (int idx = tid; idx < 64 * 8; idx += blockDim.x) {
        int j = idx >> 3, i = idx & 7;
        sW1e[idx] = W1[(128 + i) * 64 + j];
    }
    for (int idx = tid; idx < 64 * 16; idx += blockDim.x) {
        int j = idx >> 4, k = idx & 15;
        sW2[idx] = make_float2(W2[j * 32 + 2 * k], W2[j * 32 + 2 * k + 1]);
    }
    if (tid < 16) sb2[tid] = make_float2(b2v[2 * tid], b2v[2 * tid + 1]);
    if (tid < 32) sW3[tid] = W3[tid];
    if (tid == 0) sb3 = b3v[0];
    __syncthreads();

    int e = blockIdx.x * blockDim.x + tid;
    if (e >= NE) return;
    int s = esrc[e], d = edst[e];
    const float4* up = (const float4*)g_u + (size_t)s * 16;
    const float4* vp = (const float4*)g_v + (size_t)d * 16;
    const float4* ep = (const float4*)eattr + (size_t)e * 2;
    float4 ea0 = __ldg(ep);
    float4 ea1 = __ldg(ep + 1);

    unsigned long long z2[16];
    #pragma unroll
    for (int k = 0; k < 16; k++)
        z2[k] = *((const unsigned long long*)&sb2[k]);

    #pragma unroll
    for (int jv = 0; jv < 16; jv++) {
        float4 ua = __ldg(up + jv);
        float4 va = __ldg(vp + jv);
        float zt[4] = {ua.x + va.x, ua.y + va.y, ua.z + va.z, ua.w + va.w};
        #pragma unroll
        for (int t = 0; t < 4; t++) {
            int j = jv * 4 + t;
            const float* w1 = &sW1e[j * 8];
            float e1 = ea0.x * w1[0] + ea0.y * w1[1] + ea0.z * w1[2] + ea0.w * w1[3]
                     + ea1.x * w1[4] + ea1.y * w1[5] + ea1.z * w1[6] + ea1.w * w1[7];
            float z1 = fmaxf(zt[t] + e1, 0.0f);
            unsigned long long z1p;
            asm("mov.b64 %0, {%1, %1};" : "=l"(z1p) : "f"(z1));
            const unsigned long long* w2 = (const unsigned long long*)&sW2[j * 16];
            #pragma unroll
            for (int k = 0; k < 16; k++) z2[k] = ffma2(z1p, w2[k], z2[k]);
        }
    }

    float acc = sb3;
    #pragma unroll
    for (int k = 0; k < 16; k++) {
        float zx, zy;
        asm("mov.b64 {%0, %1}, %2;" : "=f"(zx), "=f"(zy) : "l"(z2[k]));
        acc += fmaxf(zx, 0.f) * sW3[2 * k] + fmaxf(zy, 0.f) * sW3[2 * k + 1];
    }
    out[e] = 1.0f / (1.0f + __expf(-acc));
}

// ---------------- launch ----------------------------------------------------
extern "C" void kernel_launch(void* const* d_in, const int* in_sizes, int n_in,
                              void* d_out, int out_size) {
    const float* x     = (const float*)d_in[0];
    const int*   eidx  = (const int*)d_in[1];
    const int*   srcv  = eidx;
    const int*   dstv  = eidx + NE;
    const float* eattr = (const float*)d_in[2];
    const float* Wl0 = (const float*)d_in[3];
    const float* bl0 = (const float*)d_in[4];
    const float* Wr0 = (const float*)d_in[5];
    const float* Wl1 = (const float*)d_in[6];
    const float* bl1 = (const float*)d_in[7];
    const float* Wr1 = (const float*)d_in[8];
    const float* Wl2 = (const float*)d_in[9];
    const float* bl2 = (const float*)d_in[10];
    const float* Wr2 = (const float*)d_in[11];
    const float* W1  = (const float*)d_in[12];
    const float* b1  = (const float*)d_in[13];
    const float* W2  = (const float*)d_in[14];
    const float* b2  = (const float*)d_in[15];
    const float* W3  = (const float*)d_in[16];
    const float* b3  = (const float*)d_in[17];
    float* out = (float*)d_out;

    float *p_mean, *p_h1, *p_h2, *p_h3;
    cudaGetSymbolAddress((void**)&p_mean, g_mean);
    cudaGetSymbolAddress((void**)&p_h1, g_h1);
    cudaGetSymbolAddress((void**)&p_h2, g_h2);
    cudaGetSymbolAddress((void**)&p_h3, g_h3);

    const int TB = 256;
    int nb = (NN + TB - 1) / TB;        // node-parallel blocks
    int eb = (NE + TB - 1) / TB;        // edge-parallel blocks
    int wb = (NN + (TB / 32) - 1) / (TB / 32);  // warp-per-node blocks

    // CSR build
    zero_cnt_kernel<<<nb, TB>>>();
    hist_kernel<<<eb, TB>>>(dstv);
    scan_kernel<<<1, 1024>>>();
    fill_kernel<<<eb, TB>>>(srcv, dstv);

    // Layer 0
    agg_kernel<32><<<wb, TB>>>(x, p_mean);
    sage_gemm_kernel<32, true><<<wb, TB>>>(p_mean, x, Wl0, bl0, Wr0, p_h1);
    // Layer 1
    agg_kernel<64><<<wb, TB>>>(p_h1, p_mean);
    sage_gemm_kernel<64, true><<<wb, TB>>>(p_mean, p_h1, Wl1, bl1, Wr1, p_h2);
    // Layer 2 (no relu)
    agg_kernel<64><<<wb, TB>>>(p_h2, p_mean);
    sage_gemm_kernel<64, false><<<wb, TB>>>(p_mean, p_h2, Wl2, bl2, Wr2, p_h3);

    // Edge predictor: per-node projections, then per-edge MLP
    uv_kernel<<<wb, TB>>>(W1, b1);
    edge_kernel<<<eb, TB>>>(srcv, dstv, eattr, W1, W2, b2, W3, b3, out);
}

// round 3
// speedup vs baseline: 1.1755x; 1.1755x over previous
#include <cuda_runtime.h>

#define NN 100000
#define NE 1600000
#define NODE_IN 32
#define HID 64

// ---------------- scratch (device globals; no runtime allocation) ----------
__device__ __align__(16) int   g_cnt[NN];
__device__ __align__(16) int   g_rowptr[NN + 1];
__device__ __align__(16) int   g_wp[NN];
__device__ __align__(16) int   g_esrc[NE];
__device__ int   g_btot[32];
__device__ int   g_boff[32];
__device__ float g_mean[(size_t)NN * HID];
__device__ float g_h1[(size_t)NN * HID];
__device__ float g_h2[(size_t)NN * HID];
__device__ float g_h3[(size_t)NN * HID];
__device__ float g_u[(size_t)NN * HID];
__device__ float g_v[(size_t)NN * HID];

// ---------------- packed f32x2 helpers -------------------------------------
__device__ __forceinline__ unsigned long long ffma2(unsigned long long a,
                                                    unsigned long long b,
                                                    unsigned long long c) {
    unsigned long long d;
    asm("fma.rn.f32x2 %0, %1, %2, %3;" : "=l"(d) : "l"(a), "l"(b), "l"(c));
    return d;
}

// ---------------- CSR build -------------------------------------------------
__global__ void zero_cnt_kernel() {
    int i = blockIdx.x * blockDim.x + threadIdx.x;
    if (i < NN) g_cnt[i] = 0;
}

__global__ void hist_kernel(const int* __restrict__ dst) {
    int e = blockIdx.x * blockDim.x + threadIdx.x;
    if (e < NE) atomicAdd(&g_cnt[dst[e]], 1);
}

// 3-phase scan: 25 blocks x 4096 elements (int4 per thread)
__global__ void scan_local_kernel() {
    __shared__ int wsum[32];
    int tid = threadIdx.x;
    int lane = tid & 31, wid = tid >> 5;
    int base = blockIdx.x * 4096 + tid * 4;
    int4 v = make_int4(0, 0, 0, 0);
    if (base < NN) v = *(const int4*)&g_cnt[base];
    int s3 = v.x + v.y + v.z + v.w;
    int x = s3;
    #pragma unroll
    for (int o = 1; o < 32; o <<= 1) {
        int t = __shfl_up_sync(0xffffffffu, x, o);
        if (lane >= o) x += t;
    }
    if (lane == 31) wsum[wid] = x;
    __syncthreads();
    if (wid == 0) {
        int ws = wsum[lane];
        #pragma unroll
        for (int o = 1; o < 32; o <<= 1) {
            int t = __shfl_up_sync(0xffffffffu, ws, o);
            if (lane >= o) ws += t;
        }
        wsum[lane] = ws;
    }
    __syncthreads();
    int excl = (x - s3) + (wid > 0 ? wsum[wid - 1] : 0);
    if (base < NN) {
        int4 r;
        r.x = excl;
        r.y = r.x + v.x;
        r.z = r.y + v.y;
        r.w = r.z + v.z;
        *(int4*)&g_rowptr[base] = r;
    }
    if (tid == 0) g_btot[blockIdx.x] = wsum[31];
}

__global__ void scan_spine_kernel() {
    int t = threadIdx.x;
    int v = (t < 25) ? g_btot[t] : 0;
    int x = v;
    #pragma unroll
    for (int o = 1; o < 32; o <<= 1) {
        int tt = __shfl_up_sync(0xffffffffu, x, o);
        if (t >= o) x += tt;
    }
    if (t < 25) g_boff[t] = x - v;
    if (t == 0) g_rowptr[NN] = NE;
}

__global__ void scan_add_kernel() {
    int base = blockIdx.x * 4096 + threadIdx.x * 4;
    if (base < NN) {
        int off = g_boff[blockIdx.x];
        int4 r = *(const int4*)&g_rowptr[base];
        r.x += off; r.y += off; r.z += off; r.w += off;
        *(int4*)&g_rowptr[base] = r;
        *(int4*)&g_wp[base] = r;
    }
}

__global__ void fill_kernel(const int* __restrict__ src, const int* __restrict__ dst) {
    int e = blockIdx.x * blockDim.x + threadIdx.x;
    if (e < NE) {
        int pos = atomicAdd(&g_wp[dst[e]], 1);
        g_esrc[pos] = src[e];
    }
}

// ---------------- mean aggregation (warp per node, gather-only) ------------
template <int F>
__global__ void agg_kernel(const float* __restrict__ h, float* __restrict__ out) {
    int warp = (blockIdx.x * blockDim.x + threadIdx.x) >> 5;
    if (warp >= NN) return;
    int lane = threadIdx.x & 31;
    int beg = g_rowptr[warp];
    int end = g_rowptr[warp + 1];
    int deg = end - beg;
    float inv = 1.0f / (float)(deg > 0 ? deg : 1);
    if (F == 64) {
        float2 a0 = make_float2(0.f, 0.f), a1 = make_float2(0.f, 0.f);
        float2 a2 = make_float2(0.f, 0.f), a3 = make_float2(0.f, 0.f);
        for (int cb = beg; cb < end; cb += 32) {
            int m = min(32, end - cb);
            int sl = g_esrc[cb + ((lane < m) ? lane : 0)];
            int j = 0;
            for (; j + 4 <= m; j += 4) {
                int s0 = __shfl_sync(0xffffffffu, sl, j);
                int s1 = __shfl_sync(0xffffffffu, sl, j + 1);
                int s2 = __shfl_sync(0xffffffffu, sl, j + 2);
                int s3 = __shfl_sync(0xffffffffu, sl, j + 3);
                float2 v0 = __ldg(((const float2*)h) + (size_t)s0 * 32 + lane);
                float2 v1 = __ldg(((const float2*)h) + (size_t)s1 * 32 + lane);
                float2 v2 = __ldg(((const float2*)h) + (size_t)s2 * 32 + lane);
                float2 v3 = __ldg(((const float2*)h) + (size_t)s3 * 32 + lane);
                a0.x += v0.x; a0.y += v0.y;
                a1.x += v1.x; a1.y += v1.y;
                a2.x += v2.x; a2.y += v2.y;
                a3.x += v3.x; a3.y += v3.y;
            }
            for (; j < m; j++) {
                int s0 = __shfl_sync(0xffffffffu, sl, j);
                float2 v0 = __ldg(((const float2*)h) + (size_t)s0 * 32 + lane);
                a0.x += v0.x; a0.y += v0.y;
            }
        }
        float2 r = make_float2(((a0.x + a1.x) + (a2.x + a3.x)) * inv,
                               ((a0.y + a1.y) + (a2.y + a3.y)) * inv);
        ((float2*)out)[(size_t)warp * 32 + lane] = r;
    } else {  // F == 32
        float a0 = 0.f, a1 = 0.f, a2 = 0.f, a3 = 0.f;
        for (int cb = beg; cb < end; cb += 32) {
            int m = min(32, end - cb);
            int sl = g_esrc[cb + ((lane < m) ? lane : 0)];
            int j = 0;
            for (; j + 4 <= m; j += 4) {
                int s0 = __shfl_sync(0xffffffffu, sl, j);
                int s1 = __shfl_sync(0xffffffffu, sl, j + 1);
                int s2 = __shfl_sync(0xffffffffu, sl, j + 2);
                int s3 = __shfl_sync(0xffffffffu, sl, j + 3);
                a0 += __ldg(h + (size_t)s0 * 32 + lane);
                a1 += __ldg(h + (size_t)s1 * 32 + lane);
                a2 += __ldg(h + (size_t)s2 * 32 + lane);
                a3 += __ldg(h + (size_t)s3 * 32 + lane);
            }
            for (; j < m; j++) {
                int s0 = __shfl_sync(0xffffffffu, sl, j);
                a0 += __ldg(h + (size_t)s0 * 32 + lane);
            }
        }
        out[(size_t)warp * 32 + lane] = ((a0 + a1) + (a2 + a3)) * inv;
    }
}

// ---------------- fused SAGE linear: out = [relu](mean@Wl + bl + h@Wr) -----
template <int FIN, bool RELU>
__global__ void sage_gemm_kernel(const float* __restrict__ mean,
                                 const float* __restrict__ h,
                                 const float* __restrict__ Wl,
                                 const float* __restrict__ bl,
                                 const float* __restrict__ Wr,
                                 float* __restrict__ out) {
    __shared__ float4 sW[FIN][32];  // (Wl[k][j], Wr[k][j], Wl[k][j+32], Wr[k][j+32])
    for (int idx = threadIdx.x; idx < FIN * 32; idx += blockDim.x) {
        int k = idx >> 5, j = idx & 31;
        sW[k][j] = make_float4(Wl[k * 64 + j], Wr[k * 64 + j],
                               Wl[k * 64 + j + 32], Wr[k * 64 + j + 32]);
    }
    __syncthreads();
    int node = blockIdx.x * (blockDim.x >> 5) + (threadIdx.x >> 5);
    if (node >= NN) return;
    int lane = threadIdx.x & 31;
    const float4* mrow = (const float4*)(mean + (size_t)node * FIN);
    const float4* hrow = (const float4*)(h + (size_t)node * FIN);
    float a0 = __ldg(bl + lane);
    float a1 = __ldg(bl + lane + 32);
    #pragma unroll 4
    for (int kv = 0; kv < FIN / 4; kv++) {
        float4 m4 = __ldg(mrow + kv);
        float4 h4 = __ldg(hrow + kv);
        {
            float4 w = sW[4 * kv + 0][lane];
            a0 += m4.x * w.x + h4.x * w.y; a1 += m4.x * w.z + h4.x * w.w;
        }
        {
            float4 w = sW[4 * kv + 1][lane];
            a0 += m4.y * w.x + h4.y * w.y; a1 += m4.y * w.z + h4.y * w.w;
        }
        {
            float4 w = sW[4 * kv + 2][lane];
            a0 += m4.z * w.x + h4.z * w.y; a1 += m4.z * w.z + h4.z * w.w;
        }
        {
            float4 w = sW[4 * kv + 3][lane];
            a0 += m4.w * w.x + h4.w * w.y; a1 += m4.w * w.z + h4.w * w.w;
        }
    }
    if (RELU) { a0 = fmaxf(a0, 0.f); a1 = fmaxf(a1, 0.f); }
    out[(size_t)node * 64 + lane] = a0;
    out[(size_t)node * 64 + lane + 32] = a1;
}

// ---------------- per-node edge-MLP precompute: U = h@W1a + b1, V = h@W1b --
__global__ void uv_kernel(const float* __restrict__ W1, const float* __restrict__ b1) {
    __shared__ float4 sW[64][32];
    for (int idx = threadIdx.x; idx < 64 * 32; idx += blockDim.x) {
        int k = idx >> 5, j = idx & 31;
        sW[k][j] = make_float4(W1[k * 64 + j], W1[(64 + k) * 64 + j],
                               W1[k * 64 + j + 32], W1[(64 + k) * 64 + j + 32]);
    }
    __syncthreads();
    int node = blockIdx.x * (blockDim.x >> 5) + (threadIdx.x >> 5);
    if (node >= NN) return;
    int lane = threadIdx.x & 31;
    const float4* hrow = (const float4*)(g_h3 + (size_t)node * 64);
    float u0 = __ldg(b1 + lane), u1 = __ldg(b1 + lane + 32);
    float v0 = 0.f, v1 = 0.f;
    #pragma unroll 4
    for (int kv = 0; kv < 16; kv++) {
        float4 h4 = __ldg(hrow + kv);
        {
            float4 w = sW[4 * kv + 0][lane];
            u0 += h4.x * w.x; v0 += h4.x * w.y; u1 += h4.x * w.z; v1 += h4.x * w.w;
        }
        {
            float4 w = sW[4 * kv + 1][lane];
            u0 += h4.y * w.x; v0 += h4.y * w.y; u1 += h4.y * w.z; v1 += h4.y * w.w;
        }
        {
            float4 w = sW[4 * kv + 2][lane];
            u0 += h4.z * w.x; v0 += h4.z * w.y; u1 += h4.z * w.z; v1 += h4.z * w.w;
        }
        {
            float4 w = sW[4 * kv + 3][lane];
            u0 += h4.w * w.x; v0 += h4.w * w.y; u1 += h4.w * w.z; v1 += h4.w * w.w;
        }
    }
    g_u[(size_t)node * 64 + lane] = u0;
    g_u[(size_t)node * 64 + lane + 32] = u1;
    g_v[(size_t)node * 64 + lane] = v0;
    g_v[(size_t)node * 64 + lane + 32] = v1;
}

// ---------------- edge MLP: warp-cooperative gather + per-thread MLP -------
// Block = 128 threads = 128 edges. Gather phase: each warp loads its 32 edges'
// U[s]+V[d] rows warp-wide (LDG.64 per row, coalesced) into a bank-padded
// shared tile (stride 68 floats). Compute phase: thread-per-edge MLP reads its
// own padded row (conflict-free LDS.128) + broadcast weights.
#define EPT 68  // padded row stride in floats
__global__ __launch_bounds__(128)
void edge_kernel(const int* __restrict__ esrc, const int* __restrict__ edst,
                 const float* __restrict__ eattr,
                 const float* __restrict__ W1, const float* __restrict__ W2,
                 const float* __restrict__ b2v, const float* __restrict__ W3,
                 const float* __restrict__ b3v, float* __restrict__ out) {
    __shared__ __align__(16) float tile[128 * EPT];
    __shared__ float  sW1e[64 * 8];   // [j*8 + i] = W1[(128+i)*64 + j]
    __shared__ float2 sW2[64 * 16];   // [j*16 + k] = (W2[j][2k], W2[j][2k+1])
    __shared__ float2 sb2[16];
    __shared__ float  sW3[32];
    __shared__ float  sb3;
    int tid = threadIdx.x, lane = tid & 31, wid = tid >> 5;
    for (int idx = tid; idx < 64 * 8; idx += 128) {
        int j = idx >> 3, i = idx & 7;
        sW1e[idx] = W1[(128 + i) * 64 + j];
    }
    for (int idx = tid; idx < 64 * 16; idx += 128) {
        int j = idx >> 4, k = idx & 15;
        sW2[idx] = make_float2(W2[j * 32 + 2 * k], W2[j * 32 + 2 * k + 1]);
    }
    if (tid < 16) sb2[tid] = make_float2(b2v[2 * tid], b2v[2 * tid + 1]);
    if (tid < 32) sW3[tid] = W3[tid];
    if (tid == 0) sb3 = b3v[0];
    __syncthreads();

    int ebase = blockIdx.x * 128;
    // ---- gather: warp handles edges [ebase + wid*32, +32)
    int eg = ebase + wid * 32 + lane;       // NE % 128 == 0: always valid
    int sl = esrc[eg];
    int dl = edst[eg];
    const float2* U2 = (const float2*)g_u;
    const float2* V2 = (const float2*)g_v;
    float* twarp = &tile[(wid * 32) * EPT];
    #pragma unroll 4
    for (int j = 0; j < 32; j++) {
        int s = __shfl_sync(0xffffffffu, sl, j);
        int d = __shfl_sync(0xffffffffu, dl, j);
        float2 u = __ldg(U2 + (size_t)s * 32 + lane);
        float2 v = __ldg(V2 + (size_t)d * 32 + lane);
        *(float2*)&twarp[j * EPT + lane * 2] = make_float2(u.x + v.x, u.y + v.y);
    }
    __syncwarp();

    // ---- compute: thread-per-edge
    int e = ebase + tid;
    const float4* ep = (const float4*)eattr + (size_t)e * 2;
    float4 ea0 = __ldg(ep);
    float4 ea1 = __ldg(ep + 1);
    const float* trow = &tile[tid * EPT];

    unsigned long long z2[16];
    #pragma unroll
    for (int k = 0; k < 16; k++)
        z2[k] = *((const unsigned long long*)&sb2[k]);

    #pragma unroll
    for (int jv = 0; jv < 16; jv++) {
        float4 uv4 = *(const float4*)(trow + jv * 4);
        float zt[4] = {uv4.x, uv4.y, uv4.z, uv4.w};
        #pragma unroll
        for (int t = 0; t < 4; t++) {
            int j = jv * 4 + t;
            const float* w1 = &sW1e[j * 8];
            float e1 = ea0.x * w1[0] + ea0.y * w1[1] + ea0.z * w1[2] + ea0.w * w1[3]
                     + ea1.x * w1[4] + ea1.y * w1[5] + ea1.z * w1[6] + ea1.w * w1[7];
            float z1 = fmaxf(zt[t] + e1, 0.0f);
            unsigned long long z1p;
            asm("mov.b64 %0, {%1, %1};" : "=l"(z1p) : "f"(z1));
            const unsigned long long* w2 = (const unsigned long long*)&sW2[j * 16];
            #pragma unroll
            for (int k = 0; k < 16; k++) z2[k] = ffma2(z1p, w2[k], z2[k]);
        }
    }

    float acc = sb3;
    #pragma unroll
    for (int k = 0; k < 16; k++) {
        float zx, zy;
        asm("mov.b64 {%0, %1}, %2;" : "=f"(zx), "=f"(zy) : "l"(z2[k]));
        acc += fmaxf(zx, 0.f) * sW3[2 * k] + fmaxf(zy, 0.f) * sW3[2 * k + 1];
    }
    out[e] = 1.0f / (1.0f + __expf(-acc));
}

// ---------------- launch ----------------------------------------------------
extern "C" void kernel_launch(void* const* d_in, const int* in_sizes, int n_in,
                              void* d_out, int out_size) {
    const float* x     = (const float*)d_in[0];
    const int*   eidx  = (const int*)d_in[1];
    const int*   srcv  = eidx;
    const int*   dstv  = eidx + NE;
    const float* eattr = (const float*)d_in[2];
    const float* Wl0 = (const float*)d_in[3];
    const float* bl0 = (const float*)d_in[4];
    const float* Wr0 = (const float*)d_in[5];
    const float* Wl1 = (const float*)d_in[6];
    const float* bl1 = (const float*)d_in[7];
    const float* Wr1 = (const float*)d_in[8];
    const float* Wl2 = (const float*)d_in[9];
    const float* bl2 = (const float*)d_in[10];
    const float* Wr2 = (const float*)d_in[11];
    const float* W1  = (const float*)d_in[12];
    const float* b1  = (const float*)d_in[13];
    const float* W2  = (const float*)d_in[14];
    const float* b2  = (const float*)d_in[15];
    const float* W3  = (const float*)d_in[16];
    const float* b3  = (const float*)d_in[17];
    float* out = (float*)d_out;

    float *p_mean, *p_h1, *p_h2, *p_h3;
    cudaGetSymbolAddress((void**)&p_mean, g_mean);
    cudaGetSymbolAddress((void**)&p_h1, g_h1);
    cudaGetSymbolAddress((void**)&p_h2, g_h2);
    cudaGetSymbolAddress((void**)&p_h3, g_h3);

    const int TB = 256;
    int nb = (NN + TB - 1) / TB;
    int eb = (NE + TB - 1) / TB;
    int wb = (NN + (TB / 32) - 1) / (TB / 32);

    // CSR build
    zero_cnt_kernel<<<nb, TB>>>();
    hist_kernel<<<eb, TB>>>(dstv);
    scan_local_kernel<<<25, 1024>>>();
    scan_spine_kernel<<<1, 32>>>();
    scan_add_kernel<<<25, 1024>>>();
    fill_kernel<<<eb, TB>>>(srcv, dstv);

    // Layer 0
    agg_kernel<32><<<wb, TB>>>(x, p_mean);
    sage_gemm_kernel<32, true><<<wb, TB>>>(p_mean, x, Wl0, bl0, Wr0, p_h1);
    // Layer 1
    agg_kernel<64><<<wb, TB>>>(p_h1, p_mean);
    sage_gemm_kernel<64, true><<<wb, TB>>>(p_mean, p_h1, Wl1, bl1, Wr1, p_h2);
    // Layer 2 (no relu)
    agg_kernel<64><<<wb, TB>>>(p_h2, p_mean);
    sage_gemm_kernel<64, false><<<wb, TB>>>(p_mean, p_h2, Wl2, bl2, Wr2, p_h3);

    // Edge predictor
    uv_kernel<<<wb, TB>>>(W1, b1);
    edge_kernel<<<NE / 128, 128>>>(srcv, dstv, eattr, W1, W2, b2, W3, b3, out);
}